// round 15
// baseline (speedup 1.0000x reference)
#include <cuda_runtime.h>

// Problem shapes (fixed)
#define BB 32
#define NN 4096
#define DD 8
#define NEE 2048
#define DEE 4
#define NSPLIT 8
#define GXB 16                         // gather blocks along N
#define DONE_TARGET (GXB * NSPLIT)     // gather blocks per batch = 128

#define FXSCALE 2097152.0f             // 2^21
#define FXINV   (1.0f / 2097152.0f)

// Device scratch (static globals; no allocation). Zero-initialized at module
// load; every kernel_launch call restores masks/counters to zero, so the
// sequence is deterministic call-to-call.
__device__ unsigned g_mask_int[NN];
__device__ unsigned g_mask_ext[NEE];
__device__ long long g_list[BB][6784];   // premultiplied byte offsets rel. W_int
__device__ int g_cnt[BB];                // padded combined length (multiple of 16)
__device__ int g_acc[BB][NN];            // fixed-point accumulator (seeded by spike)
__device__ int g_done[BB];               // gather arrival counters (reset by converter)
__device__ float g_zero[NN];             // stays all-zero; pad rows point here

// ---------------------------------------------------------------------------
// Kernel 1 (fused spike + mask + accumulator seed): thread per (b,n).
// ---------------------------------------------------------------------------
__global__ void k_spikemask(const float* __restrict__ V, const float* __restrict__ a,
                            const float* __restrict__ Xd, const float* __restrict__ Xext,
                            const float* __restrict__ dmap_int,
                            const float* __restrict__ dmap_ext,
                            float* __restrict__ out) {
    int idx = blockIdx.x * blockDim.x + threadIdx.x;   // 0 .. B*N-1
    int b = idx >> 12;                                 // idx / NN
    int n = idx & (NN - 1);

    float v  = V[idx];
    float aa = a[idx];
    float th = __fadd_rn(1.0f, __fmul_rn(1.8f, aa));
    float x  = (__fadd_rn(v, -th) >= 0.0f) ? 1.0f : 0.0f;
    out[idx] = x;                                       // row 0: X
    out[2 * BB * NN + idx] = 0.98f * aa + x;            // row 2: a_new

    // seed fixed-point accumulator with the leak/reset term
    g_acc[b][n] = __float2int_rn(0.95f * v * (1.0f - x) * FXSCALE);

    // internal source (b, n)
    {
        int del = 0;
#pragma unroll
        for (int d = 0; d < DD; d++)
            if (dmap_int[d * NN + n] > 0.5f) del = d;
        float xs = (del == 0) ? x : Xd[(size_t)(del - 1) * BB * NN + idx];
        if (xs > 0.5f) atomicOr(&g_mask_int[n], 1u << b);
    }
    // external source (b, n) for n < NE
    if (n < NEE) {
        int del = 0;
#pragma unroll
        for (int d = 0; d < DEE; d++)
            if (dmap_ext[d * NEE + n] > 0.5f) del = d;
        float xs = Xext[(size_t)del * BB * NEE + b * NEE + n];
        if (xs > 0.5f) atomicOr(&g_mask_ext[n], 1u << b);
    }
}

// ---------------------------------------------------------------------------
// Kernel 2: compaction into ONE combined offset list per batch, then re-zero
// the consumed masks (each block owns its slice) for the next call.
// ---------------------------------------------------------------------------
__global__ void __launch_bounds__(256) k_compact(const float* __restrict__ W_int,
                                                 const float* __restrict__ W_ext) {
    int b = blockIdx.x;            // 0..31
    int tid = threadIdx.x;
    int w = tid >> 5, lane = tid & 31;
    unsigned lt = (lane == 0) ? 0u : (0xffffffffu >> (32 - lane));

    const long long ext_base = (long long)((const char*)W_ext - (const char*)W_int);
    const long long zero_off = (long long)((const char*)g_zero - (const char*)W_int);

    __shared__ int wcnt[8], wbase[8], s_total, s_base_ext;

    // ---- internal ----
    {
        int cnt = 0;
#pragma unroll
        for (int r = 0; r < 16; r++) {
            int i = (w * 16 + r) * 32 + lane;
            bool act = (g_mask_int[i] >> b) & 1u;
            cnt += __popc(__ballot_sync(0xffffffffu, act));
        }
        if (lane == 0) wcnt[w] = cnt;
        __syncthreads();
        if (tid == 0) {
            int s = 0;
#pragma unroll
            for (int j = 0; j < 8; j++) { wbase[j] = s; s += wcnt[j]; }
            s_total = s;
            s_base_ext = s;
        }
        __syncthreads();
        int base = wbase[w];
#pragma unroll
        for (int r = 0; r < 16; r++) {
            int i = (w * 16 + r) * 32 + lane;
            bool act = (g_mask_int[i] >> b) & 1u;
            unsigned bal = __ballot_sync(0xffffffffu, act);
            if (act) g_list[b][base + __popc(bal & lt)] = (long long)i * (NN * 4);
            base += __popc(bal);
        }
        __syncthreads();
    }

    // ---- external (appended) ----
    {
        int cnt = 0;
#pragma unroll
        for (int r = 0; r < 8; r++) {
            int i = (w * 8 + r) * 32 + lane;
            bool act = (g_mask_ext[i] >> b) & 1u;
            cnt += __popc(__ballot_sync(0xffffffffu, act));
        }
        if (lane == 0) wcnt[w] = cnt;
        __syncthreads();
        if (tid == 0) {
            int s = s_base_ext;
#pragma unroll
            for (int j = 0; j < 8; j++) { wbase[j] = s; s += wcnt[j]; }
            s_total = s;
        }
        __syncthreads();
        int base = wbase[w];
#pragma unroll
        for (int r = 0; r < 8; r++) {
            int i = (w * 8 + r) * 32 + lane;
            bool act = (g_mask_ext[i] >> b) & 1u;
            unsigned bal = __ballot_sync(0xffffffffu, act);
            if (act) g_list[b][base + __popc(bal & lt)] = ext_base + (long long)i * (NN * 4);
            base += __popc(bal);
        }
        __syncthreads();
        int t = s_total;
        int padded = (t + 15) & ~15;
        if (t + tid < padded) g_list[b][t + tid] = zero_off;
        if (tid == 0) g_cnt[b] = padded;
    }

    // ---- re-zero masks for the next call (each block owns a 1/32 slice) ----
    __syncthreads();
    {
        int per = NN / BB;            // 128
        if (tid < per) g_mask_int[b * per + tid] = 0u;
        int per_e = NEE / BB;         // 64
        if (tid < per_e) g_mask_ext[b * per_e + tid] = 0u;
    }
}

// ---------------------------------------------------------------------------
// Kernel 3: split-K sparse row-gather (float2, proven body) + deterministic
// fixed-point accumulation + last-block-per-batch conversion.
// grid (GXB, B, NSPLIT), 128 threads. Int atomics are exact and
// order-independent -> bitwise-deterministic output.
// ---------------------------------------------------------------------------
__global__ void k_gather(const float* __restrict__ W_int,
                         float* __restrict__ out) {
    __shared__ int s_last;

    const int b = blockIdx.y;
    const int s = blockIdx.z;
    const int nwin = g_cnt[b] >> 4;
    const long long* __restrict__ lst = g_list[b];

    const int n2 = (blockIdx.x * 128 + threadIdx.x) * 2;  // column pair
    const char* base = (const char*)W_int + (size_t)n2 * 4;

    float ax0 = 0.f, ay0 = 0.f, ax1 = 0.f, ay1 = 0.f;
    float ax2 = 0.f, ay2 = 0.f, ax3 = 0.f, ay3 = 0.f;

    for (int j = s; j < nwin; j += NSPLIT) {
        const int k = j * 16;
        long long o[16];
#pragma unroll
        for (int u = 0; u < 16; u++) o[u] = __ldg(lst + k + u);
        float2 w[16];
#pragma unroll
        for (int u = 0; u < 16; u++)
            w[u] = __ldg((const float2*)(base + o[u]));
#pragma unroll
        for (int u = 0; u < 16; u += 4) {
            ax0 += w[u].x;     ay0 += w[u].y;
            ax1 += w[u + 1].x; ay1 += w[u + 1].y;
            ax2 += w[u + 2].x; ay2 += w[u + 2].y;
            ax3 += w[u + 3].x; ay3 += w[u + 3].y;
        }
    }

    float rx = (ax0 + ax1) + (ax2 + ax3);
    float ry = (ay0 + ay1) + (ay2 + ay3);

    // deterministic fixed-point accumulation (exact integer adds)
    atomicAdd(&g_acc[b][n2],     __float2int_rn(rx * FXSCALE));
    atomicAdd(&g_acc[b][n2 + 1], __float2int_rn(ry * FXSCALE));
    __threadfence();
    __syncthreads();

    if (threadIdx.x == 0) {
        int done = atomicAdd(&g_done[b], 1);
        s_last = (done == DONE_TARGET - 1) ? 1 : 0;
    }
    __syncthreads();

    if (s_last) {
        // This is the last gather block for batch b: all g_acc[b][*] adds are
        // globally visible (threadfence + L2 atomics). Convert to float.
        float* dst = out + BB * NN + b * NN;
        for (int i = threadIdx.x; i < NN; i += 128) {
            int q;
            asm volatile("ld.global.cg.b32 %0, [%1];" : "=r"(q) : "l"(&g_acc[b][i]));
            dst[i] = (float)q * FXINV;
        }
        if (threadIdx.x == 0) g_done[b] = 0;   // reset for next call
    }
}

// ---------------------------------------------------------------------------
extern "C" void kernel_launch(void* const* d_in, const int* in_sizes, int n_in,
                              void* d_out, int out_size) {
    const float* V        = (const float*)d_in[0];   // [B,N]
    const float* a        = (const float*)d_in[1];   // [B,N]
    const float* Xd       = (const float*)d_in[2];   // [D,B,N]
    const float* Xext     = (const float*)d_in[3];   // [DE,B,NE]
    const float* W_int    = (const float*)d_in[4];   // [N,N]
    const float* W_ext    = (const float*)d_in[5];   // [NE,N]
    const float* dmap_int = (const float*)d_in[6];   // [D,N]
    const float* dmap_ext = (const float*)d_in[7];   // [DE,NE]
    float* out = (float*)d_out;                      // [3,B,N]

    k_spikemask<<<(BB * NN) / 256, 256>>>(V, a, Xd, Xext, dmap_int, dmap_ext, out);
    k_compact<<<BB, 256>>>(W_int, W_ext);
    dim3 grid(GXB, BB, NSPLIT);
    k_gather<<<grid, 128>>>(W_int, out);
}